// round 9
// baseline (speedup 1.0000x reference)
#include <cuda_runtime.h>
#include <cuda_fp16.h>

// DynamicDilationUnfold R9: R8 + occupancy push (5 blocks/SM, 51-reg budget),
// minimal live-range tap evaluation, 32-bit output offsets.
// B=4, C=64, H=W=128, G=4, Cg=16, K=3, pad=1, stride=1.

#define B_    4
#define C_    64
#define H_    128
#define W_    128
#define G_    4
#define CG_   16
#define HW_   (H_ * W_)          // 16384
#define NC8   2                  // channel octets per group (16/8)
#define NROWS 8                  // rows hb-1 .. hb+6 (2 out rows, d < 3.0)
#define WP    (W_ + 1)           // padded row (bank stagger)
#define TT    9                  // taps per channel
#define CS    (TT * HW_)         // out channel stride (elements)

__device__ __forceinline__ __half2 u2h(unsigned int u) {
    return *reinterpret_cast<__half2*>(&u);
}
__device__ __forceinline__ unsigned int h2u(__half2 h) {
    return *reinterpret_cast<unsigned int*>(&h);
}
__device__ __forceinline__ __half2 lerpu(__half2 w0, __half2 w1,
                                         unsigned int a, unsigned int b) {
    return __hfma2(w1, u2h(b), __hmul2(w0, u2h(a)));
}
__device__ __forceinline__ __half2 lerph(__half2 w0, __half2 w1,
                                         __half2 a, __half2 b) {
    return __hfma2(w1, b, __hmul2(w0, a));
}

// store 8 channels (4 half2) of one tap; 32-bit offsets
__device__ __forceinline__ void st8(float* __restrict__ o, unsigned int off,
                                    __half2 a, __half2 b, __half2 c, __half2 e)
{
    float* p = o + off;
    float2 f;
    f = __half22float2(a); p[0]      = f.x; p[1u * CS] = f.y;
    f = __half22float2(b); p[2u * CS] = f.x; p[3u * CS] = f.y;
    f = __half22float2(c); p[4u * CS] = f.x; p[5u * CS] = f.y;
    f = __half22float2(e); p[6u * CS] = f.x; p[7u * CS] = f.y;
}

__global__ __launch_bounds__(256, 5)
void ddunfold_kernel(const float* __restrict__ x,
                     const float* __restrict__ dmap,
                     float* __restrict__ out)
{
    __shared__ uint4 tile[NC8][NROWS][WP];   // 33,024 B

    const int wo = threadIdx.x & (W_ - 1);   // 0..127
    const int ty = threadIdx.x >> 7;         // 0/1
    const int hb = blockIdx.x << 1;          // ho base (even)
    const int g  = blockIdx.y;               // 0..3
    const int b  = blockIdx.z;               // 0..3

    const int ho = hb + ty;
    const float d = dmap[((b * G_ + g) * H_ + ho) * W_ + wo];  // early load

    // ---- fused fill: fp32 planar -> half8 (uint4) packed smem rows ----
    const float* __restrict__ xg = x + (size_t)(b * C_ + g * CG_) * HW_;
    #pragma unroll
    for (int i = 0; i < 8; i++) {
        const int combo = 2 * i + ty;        // 0..15
        const int c8 = combo >> 3;
        const int j  = combo & 7;
        const int gr = min(max(hb - 1 + j, 0), H_ - 1);
        const float* xp = xg + (unsigned)(c8 * 8) * HW_ + gr * W_ + wo;
        uint4 v;
        v.x = h2u(__floats2half2_rn(__ldg(xp),           __ldg(xp + HW_)));
        v.y = h2u(__floats2half2_rn(__ldg(xp + 2 * HW_), __ldg(xp + 3 * HW_)));
        v.z = h2u(__floats2half2_rn(__ldg(xp + 4 * HW_), __ldg(xp + 5 * HW_)));
        v.w = h2u(__floats2half2_rn(__ldg(xp + 6 * HW_), __ldg(xp + 7 * HW_)));
        tile[c8][j][wo] = v;
    }

    // ---- k=0: exact integer tap at (ho-1, wo-1) ----
    const __half2 mh0 = __float2half2_rn(ho >= 1 ? 1.0f : 0.0f);
    const __half2 mw0 = __float2half2_rn(wo >= 1 ? 1.0f : 0.0f);
    const __half2 m00 = __hmul2(mh0, mw0);
    const int wm1 = max(wo - 1, 0);

    // ---- k=1,2: separable weights + smem indices ----
    __half2 ah0h[2], ah1h[2], bw0h[2], bw1h[2];
    int jh0[2], jh1[2], w0c[2], w1c[2];

    #pragma unroll
    for (int kk = 0; kk < 2; kk++) {
        const float kf = (float)(kk + 1);
        { // h axis
            const float p  = (float)(ho - 1) + kf * d;
            const float f0 = floorf(p);
            const float l  = p - f0;
            const bool  v0 = (f0 >= 0.0f)  && (f0 <= (float)(H_ - 1));
            const bool  v1 = (f0 >= -1.0f) && (f0 <= (float)(H_ - 2));
            ah0h[kk] = __float2half2_rn(v0 ? (1.0f - l) : 0.0f);
            ah1h[kk] = __float2half2_rn(v1 ? l : 0.0f);
            const int j = (int)f0 - (hb - 1);
            jh0[kk] = min(max(j,     0), NROWS - 1);
            jh1[kk] = min(max(j + 1, 0), NROWS - 1);
        }
        { // w axis
            const float p  = (float)(wo - 1) + kf * d;
            const float f0 = floorf(p);
            const float l  = p - f0;
            const bool  v0 = (f0 >= 0.0f)  && (f0 <= (float)(W_ - 1));
            const bool  v1 = (f0 >= -1.0f) && (f0 <= (float)(W_ - 2));
            bw0h[kk] = __float2half2_rn(v0 ? (1.0f - l) : 0.0f);
            bw1h[kk] = __float2half2_rn(v1 ? l : 0.0f);
            const int i0 = (int)f0;
            w0c[kk] = min(max(i0,     0), W_ - 1);
            w1c[kk] = min(max(i0 + 1, 0), W_ - 1);
        }
    }

    __syncthreads();

    const int pix = ho * W_ + wo;
    float* __restrict__ ob = out + ((size_t)(b * C_ + g * CG_)) * CS + pix;

    #pragma unroll
    for (int c8 = 0; c8 < NC8; c8++) {
        float* __restrict__ oc = ob + (unsigned)(c8 * 8) * CS;

        // tap (0,0): direct copy with border mask
        {
            const uint4 q = tile[c8][ty][wm1];
            st8(oc, 0,
                __hmul2(m00, u2h(q.x)), __hmul2(m00, u2h(q.y)),
                __hmul2(m00, u2h(q.z)), __hmul2(m00, u2h(q.w)));
        }

        // taps (0,kw), kw=1,2: horizontal lerp on row ho-1 (mask mh0)
        #pragma unroll
        for (int kk = 0; kk < 2; kk++) {
            const uint4 q0 = tile[c8][ty][w0c[kk]];
            const uint4 q1 = tile[c8][ty][w1c[kk]];
            const __half2 wa = __hmul2(mh0, bw0h[kk]);
            const __half2 wb = __hmul2(mh0, bw1h[kk]);
            st8(oc, (unsigned)(kk + 1) * HW_,
                lerpu(wa, wb, q0.x, q1.x), lerpu(wa, wb, q0.y, q1.y),
                lerpu(wa, wb, q0.z, q1.z), lerpu(wa, wb, q0.w, q1.w));
        }

        // taps (kh,0), kh=1,2: vertical lerp on col wo-1 (mask mw0)
        #pragma unroll
        for (int kk = 0; kk < 2; kk++) {
            const uint4 q0 = tile[c8][jh0[kk]][wm1];
            const uint4 q1 = tile[c8][jh1[kk]][wm1];
            const __half2 wa = __hmul2(mw0, ah0h[kk]);
            const __half2 wb = __hmul2(mw0, ah1h[kk]);
            st8(oc, (unsigned)((kk + 1) * 3) * HW_,
                lerpu(wa, wb, q0.x, q1.x), lerpu(wa, wb, q0.y, q1.y),
                lerpu(wa, wb, q0.z, q1.z), lerpu(wa, wb, q0.w, q1.w));
        }

        // full bilinear taps (kh,kw), kh,kw in {1,2}
        // minimal live ranges: top row pair -> lerp -> release, then bottom.
        #pragma unroll
        for (int kh = 0; kh < 2; kh++) {
            const int r0 = jh0[kh];
            const int r1 = jh1[kh];
            #pragma unroll
            for (int kw = 0; kw < 2; kw++) {
                __half2 tx, tyv, tz, tw;
                {
                    const uint4 q00 = tile[c8][r0][w0c[kw]];
                    const uint4 q01 = tile[c8][r0][w1c[kw]];
                    tx  = lerpu(bw0h[kw], bw1h[kw], q00.x, q01.x);
                    tyv = lerpu(bw0h[kw], bw1h[kw], q00.y, q01.y);
                    tz  = lerpu(bw0h[kw], bw1h[kw], q00.z, q01.z);
                    tw  = lerpu(bw0h[kw], bw1h[kw], q00.w, q01.w);
                }
                __half2 bx, by, bz, bw2;
                {
                    const uint4 q10 = tile[c8][r1][w0c[kw]];
                    const uint4 q11 = tile[c8][r1][w1c[kw]];
                    bx  = lerpu(bw0h[kw], bw1h[kw], q10.x, q11.x);
                    by  = lerpu(bw0h[kw], bw1h[kw], q10.y, q11.y);
                    bz  = lerpu(bw0h[kw], bw1h[kw], q10.z, q11.z);
                    bw2 = lerpu(bw0h[kw], bw1h[kw], q10.w, q11.w);
                }
                st8(oc, (unsigned)((kh + 1) * 3 + (kw + 1)) * HW_,
                    lerph(ah0h[kh], ah1h[kh], tx,  bx),
                    lerph(ah0h[kh], ah1h[kh], tyv, by),
                    lerph(ah0h[kh], ah1h[kh], tz,  bz),
                    lerph(ah0h[kh], ah1h[kh], tw,  bw2));
            }
        }
    }
}

extern "C" void kernel_launch(void* const* d_in, const int* in_sizes, int n_in,
                              void* d_out, int out_size)
{
    const float* x    = (const float*)d_in[0];
    const float* dmap = (const float*)d_in[1];
    float* out        = (float*)d_out;

    dim3 grid(H_ / 2, G_, B_);   // (ho pair, g, b)
    dim3 block(256);             // 2 rows x 128 wo
    ddunfold_kernel<<<grid, block>>>(x, dmap, out);
}

// round 10
// speedup vs baseline: 1.3105x; 1.3105x over previous
#include <cuda_runtime.h>
#include <cuda_fp16.h>

// DynamicDilationUnfold R10: R8 (64-reg, 4 blocks/SM — R9 spill revert)
// + streaming (__stcs) output stores + early dmap load.
// B=4, C=64, H=W=128, G=4, Cg=16, K=3, pad=1, stride=1.

#define B_    4
#define C_    64
#define H_    128
#define W_    128
#define G_    4
#define CG_   16
#define HW_   (H_ * W_)          // 16384
#define NC8   2                  // channel octets per group (16/8)
#define NROWS 8                  // rows hb-1 .. hb+6 (2 out rows, d < 3.0)
#define WP    (W_ + 1)           // padded row (bank stagger)
#define TT    9                  // taps per channel
#define CS    (TT * HW_)         // out channel stride (elements)

__device__ __forceinline__ __half2 u2h(unsigned int u) {
    return *reinterpret_cast<__half2*>(&u);
}
__device__ __forceinline__ unsigned int h2u(__half2 h) {
    return *reinterpret_cast<unsigned int*>(&h);
}
__device__ __forceinline__ __half2 lerpu(__half2 w0, __half2 w1,
                                         unsigned int a, unsigned int b) {
    return __hfma2(w1, u2h(b), __hmul2(w0, u2h(a)));
}
__device__ __forceinline__ __half2 lerph(__half2 w0, __half2 w1,
                                         __half2 a, __half2 b) {
    return __hfma2(w1, b, __hmul2(w0, a));
}

// store 8 channels (4 half2) of one tap — streaming (evict-first)
__device__ __forceinline__ void st8(float* __restrict__ o, int tap,
                                    __half2 a, __half2 b, __half2 c, __half2 e)
{
    float* p = o + (size_t)tap * HW_;
    float2 f;
    f = __half22float2(a); __stcs(p,                  f.x); __stcs(p + 1u * CS, f.y);
    f = __half22float2(b); __stcs(p + 2u * CS, f.x);  __stcs(p + 3u * CS, f.y);
    f = __half22float2(c); __stcs(p + 4u * CS, f.x);  __stcs(p + 5u * CS, f.y);
    f = __half22float2(e); __stcs(p + 6u * CS, f.x);  __stcs(p + 7u * CS, f.y);
}

__global__ __launch_bounds__(256, 4)
void ddunfold_kernel(const float* __restrict__ x,
                     const float* __restrict__ dmap,
                     float* __restrict__ out)
{
    __shared__ uint4 tile[NC8][NROWS][WP];   // 33,024 B

    const int wo = threadIdx.x & (W_ - 1);   // 0..127
    const int ty = threadIdx.x >> 7;         // 0/1: which output row
    const int hb = blockIdx.x << 1;          // ho base (even)
    const int g  = blockIdx.y;               // 0..3
    const int b  = blockIdx.z;               // 0..3

    const int ho = hb + ty;
    const float d = dmap[((b * G_ + g) * H_ + ho) * W_ + wo];  // early load

    // ---- fused fill: fp32 planar -> half8 (uint4) packed smem rows ----
    const float* __restrict__ xg = x + (size_t)(b * C_ + g * CG_) * HW_;
    #pragma unroll
    for (int i = 0; i < 8; i++) {
        const int combo = 2 * i + ty;        // 0..15
        const int c8 = combo >> 3;           // 0..1
        const int j  = combo & 7;            // 0..7
        const int gr = min(max(hb - 1 + j, 0), H_ - 1);
        const float* xp = xg + (size_t)(c8 * 8) * HW_ + gr * W_ + wo;
        uint4 v;
        v.x = h2u(__floats2half2_rn(__ldg(xp),           __ldg(xp + HW_)));
        v.y = h2u(__floats2half2_rn(__ldg(xp + 2 * HW_), __ldg(xp + 3 * HW_)));
        v.z = h2u(__floats2half2_rn(__ldg(xp + 4 * HW_), __ldg(xp + 5 * HW_)));
        v.w = h2u(__floats2half2_rn(__ldg(xp + 6 * HW_), __ldg(xp + 7 * HW_)));
        tile[c8][j][wo] = v;
    }

    // ---- k=0: exact integer tap at (ho-1, wo-1) ----
    const __half2 mh0 = __float2half2_rn(ho >= 1 ? 1.0f : 0.0f);
    const __half2 mw0 = __float2half2_rn(wo >= 1 ? 1.0f : 0.0f);
    const __half2 m00 = __hmul2(mh0, mw0);
    const int wm1 = max(wo - 1, 0);

    // ---- k=1,2: separable weights + smem indices ----
    __half2 ah0h[2], ah1h[2], bw0h[2], bw1h[2];
    int jh0[2], jh1[2], w0c[2], w1c[2];

    #pragma unroll
    for (int kk = 0; kk < 2; kk++) {
        const float kf = (float)(kk + 1);
        { // h axis
            const float p  = (float)(ho - 1) + kf * d;
            const float f0 = floorf(p);
            const float l  = p - f0;
            const bool  v0 = (f0 >= 0.0f)  && (f0 <= (float)(H_ - 1));
            const bool  v1 = (f0 >= -1.0f) && (f0 <= (float)(H_ - 2));
            ah0h[kk] = __float2half2_rn(v0 ? (1.0f - l) : 0.0f);
            ah1h[kk] = __float2half2_rn(v1 ? l : 0.0f);
            const int j = (int)f0 - (hb - 1);
            jh0[kk] = min(max(j,     0), NROWS - 1);
            jh1[kk] = min(max(j + 1, 0), NROWS - 1);
        }
        { // w axis
            const float p  = (float)(wo - 1) + kf * d;
            const float f0 = floorf(p);
            const float l  = p - f0;
            const bool  v0 = (f0 >= 0.0f)  && (f0 <= (float)(W_ - 1));
            const bool  v1 = (f0 >= -1.0f) && (f0 <= (float)(W_ - 2));
            bw0h[kk] = __float2half2_rn(v0 ? (1.0f - l) : 0.0f);
            bw1h[kk] = __float2half2_rn(v1 ? l : 0.0f);
            const int i0 = (int)f0;
            w0c[kk] = min(max(i0,     0), W_ - 1);
            w1c[kk] = min(max(i0 + 1, 0), W_ - 1);
        }
    }

    __syncthreads();

    const int pix = ho * W_ + wo;
    float* __restrict__ ob = out + ((size_t)(b * C_ + g * CG_)) * CS + pix;

    #pragma unroll
    for (int c8 = 0; c8 < NC8; c8++) {
        float* __restrict__ oc = ob + (size_t)(c8 * 8) * CS;

        // tap (0,0): direct copy with border mask
        {
            const uint4 q = tile[c8][ty][wm1];
            st8(oc, 0,
                __hmul2(m00, u2h(q.x)), __hmul2(m00, u2h(q.y)),
                __hmul2(m00, u2h(q.z)), __hmul2(m00, u2h(q.w)));
        }

        // taps (0,kw), kw=1,2: horizontal lerp on row ho-1 (mask mh0)
        #pragma unroll
        for (int kk = 0; kk < 2; kk++) {
            const uint4 q0 = tile[c8][ty][w0c[kk]];
            const uint4 q1 = tile[c8][ty][w1c[kk]];
            const __half2 wa = __hmul2(mh0, bw0h[kk]);
            const __half2 wb = __hmul2(mh0, bw1h[kk]);
            st8(oc, kk + 1,
                lerpu(wa, wb, q0.x, q1.x), lerpu(wa, wb, q0.y, q1.y),
                lerpu(wa, wb, q0.z, q1.z), lerpu(wa, wb, q0.w, q1.w));
        }

        // taps (kh,0), kh=1,2: vertical lerp on col wo-1 (mask mw0)
        #pragma unroll
        for (int kk = 0; kk < 2; kk++) {
            const uint4 q0 = tile[c8][jh0[kk]][wm1];
            const uint4 q1 = tile[c8][jh1[kk]][wm1];
            const __half2 wa = __hmul2(mw0, ah0h[kk]);
            const __half2 wb = __hmul2(mw0, ah1h[kk]);
            st8(oc, (kk + 1) * 3,
                lerpu(wa, wb, q0.x, q1.x), lerpu(wa, wb, q0.y, q1.y),
                lerpu(wa, wb, q0.z, q1.z), lerpu(wa, wb, q0.w, q1.w));
        }

        // full bilinear taps (kh,kw), kh,kw in {1,2}
        #pragma unroll
        for (int kh = 0; kh < 2; kh++) {
            const int r0 = jh0[kh];
            const int r1 = jh1[kh];
            #pragma unroll
            for (int kw = 0; kw < 2; kw++) {
                const uint4 q00 = tile[c8][r0][w0c[kw]];
                const uint4 q01 = tile[c8][r0][w1c[kw]];
                const uint4 q10 = tile[c8][r1][w0c[kw]];
                const uint4 q11 = tile[c8][r1][w1c[kw]];

                const __half2 ox = lerph(ah0h[kh], ah1h[kh],
                                         lerpu(bw0h[kw], bw1h[kw], q00.x, q01.x),
                                         lerpu(bw0h[kw], bw1h[kw], q10.x, q11.x));
                const __half2 oy = lerph(ah0h[kh], ah1h[kh],
                                         lerpu(bw0h[kw], bw1h[kw], q00.y, q01.y),
                                         lerpu(bw0h[kw], bw1h[kw], q10.y, q11.y));
                const __half2 oz = lerph(ah0h[kh], ah1h[kh],
                                         lerpu(bw0h[kw], bw1h[kw], q00.z, q01.z),
                                         lerpu(bw0h[kw], bw1h[kw], q10.z, q11.z));
                const __half2 ow = lerph(ah0h[kh], ah1h[kh],
                                         lerpu(bw0h[kw], bw1h[kw], q00.w, q01.w),
                                         lerpu(bw0h[kw], bw1h[kw], q10.w, q11.w));

                st8(oc, (kh + 1) * 3 + (kw + 1), ox, oy, oz, ow);
            }
        }
    }
}

extern "C" void kernel_launch(void* const* d_in, const int* in_sizes, int n_in,
                              void* d_out, int out_size)
{
    const float* x    = (const float*)d_in[0];
    const float* dmap = (const float*)d_in[1];
    float* out        = (float*)d_out;

    dim3 grid(H_ / 2, G_, B_);   // (ho pair, g, b)
    dim3 block(256);             // 2 rows x 128 wo
    ddunfold_kernel<<<grid, block>>>(x, dmap, out);
}